// round 1
// baseline (speedup 1.0000x reference)
#include <cuda_runtime.h>
#include <cuda_bf16.h>
#include <cstdint>

#define B_ROWS 4096
#define D_DIM 1024
#define N2 8192
#define KC 64
#define SMEM_STRIDE 72   // bf16 units: 64 payload + 8 pad (conflict-free ldmatrix)

// exp(sim/T) = exp(2*sim) = exp2(sim * 2*log2(e))
#define EXP_SCALE 2.8853900817779268f

__device__ __nv_bfloat16 g_reps[(size_t)N2 * D_DIM];
__device__ float g_nom[N2];
__device__ float g_den[N2];

__device__ __forceinline__ uint32_t smem_u32(const void* p) {
    return (uint32_t)__cvta_generic_to_shared(p);
}

__device__ __forceinline__ void ldm_x4(uint32_t r[4], uint32_t saddr) {
    asm volatile("ldmatrix.sync.aligned.m8n8.x4.shared.b16 {%0,%1,%2,%3}, [%4];\n"
                 : "=r"(r[0]), "=r"(r[1]), "=r"(r[2]), "=r"(r[3])
                 : "r"(saddr));
}

__device__ __forceinline__ void mma_bf16(float c[4], const uint32_t a[4],
                                         uint32_t b0, uint32_t b1) {
    asm volatile(
        "mma.sync.aligned.m16n8k16.row.col.f32.bf16.bf16.f32 "
        "{%0,%1,%2,%3}, {%4,%5,%6,%7}, {%8,%9}, {%0,%1,%2,%3};\n"
        : "+f"(c[0]), "+f"(c[1]), "+f"(c[2]), "+f"(c[3])
        : "r"(a[0]), "r"(a[1]), "r"(a[2]), "r"(a[3]), "r"(b0), "r"(b1));
}

__device__ __forceinline__ float fast_exp2(float x) {
    float y;
    asm("ex2.approx.f32 %0, %1;" : "=f"(y) : "f"(x));
    return y;
}

// ---------------------------------------------------------------------------
// Kernel 0: zero the accumulators (graph replays must re-zero every call)
// ---------------------------------------------------------------------------
__global__ void zero_kernel() {
    int i = blockIdx.x * blockDim.x + threadIdx.x;
    if (i < N2) { g_nom[i] = 0.0f; g_den[i] = 0.0f; }
}

// ---------------------------------------------------------------------------
// Kernel 1: L2-normalize rows of [emb_i; emb_j] -> bf16 reps
// one block per row, 128 threads, 8 floats each
// ---------------------------------------------------------------------------
__global__ void normalize_kernel(const float* __restrict__ emb_i,
                                 const float* __restrict__ emb_j) {
    int row = blockIdx.x;
    const float* src = (row < B_ROWS)
        ? emb_i + (size_t)row * D_DIM
        : emb_j + (size_t)(row - B_ROWS) * D_DIM;
    int t = threadIdx.x;
    const float4* s4 = (const float4*)src;
    float4 v0 = s4[t];
    float4 v1 = s4[t + 128];
    float ss = v0.x * v0.x + v0.y * v0.y + v0.z * v0.z + v0.w * v0.w
             + v1.x * v1.x + v1.y * v1.y + v1.z * v1.z + v1.w * v1.w;
    #pragma unroll
    for (int s = 16; s > 0; s >>= 1)
        ss += __shfl_xor_sync(0xffffffffu, ss, s);
    __shared__ float wsum[4];
    if ((t & 31) == 0) wsum[t >> 5] = ss;
    __syncthreads();
    float total = wsum[0] + wsum[1] + wsum[2] + wsum[3];
    float scale = 1.0f / fmaxf(sqrtf(total), 1e-12f);

    __nv_bfloat162* d2 = (__nv_bfloat162*)(g_reps + (size_t)row * D_DIM);
    d2[2 * t + 0]         = __floats2bfloat162_rn(v0.x * scale, v0.y * scale);
    d2[2 * t + 1]         = __floats2bfloat162_rn(v0.z * scale, v0.w * scale);
    d2[2 * (t + 128) + 0] = __floats2bfloat162_rn(v1.x * scale, v1.y * scale);
    d2[2 * (t + 128) + 1] = __floats2bfloat162_rn(v1.z * scale, v1.w * scale);
}

// ---------------------------------------------------------------------------
// Kernel 2: fused sim-GEMM + exp + masked row sums
// CTA tile 128(M) x 128(N), K loop over 1024 in chunks of 64.
// 8 warps: 4(m) x 2(n), warp tile 32 x 64, mma.m16n8k16 bf16.
// ---------------------------------------------------------------------------
__global__ void __launch_bounds__(256, 1)
sim_kernel(const int* __restrict__ labels) {
    __shared__ __nv_bfloat16 sA[128 * SMEM_STRIDE];
    __shared__ __nv_bfloat16 sB[128 * SMEM_STRIDE];
    __shared__ int sLabN[128];

    const int bm = blockIdx.y, bn = blockIdx.x;
    const int rowbase = bm * 128, colbase = bn * 128;

    const int tid = threadIdx.x;
    const int warp = tid >> 5, lane = tid & 31;
    const int wm = warp >> 1;   // 0..3 -> m offset wm*32
    const int wn = warp & 1;    // 0..1 -> n offset wn*64

    if (tid < 128) sLabN[tid] = labels[(colbase + tid) & (B_ROWS - 1)];

    float acc[2][8][4];
    #pragma unroll
    for (int mt = 0; mt < 2; mt++)
        #pragma unroll
        for (int nt = 0; nt < 8; nt++)
            #pragma unroll
            for (int i = 0; i < 4; i++) acc[mt][nt][i] = 0.0f;

    const __nv_bfloat16* gA = g_reps + (size_t)rowbase * D_DIM;
    const __nv_bfloat16* gB = g_reps + (size_t)colbase * D_DIM;

    for (int kc = 0; kc < D_DIM; kc += KC) {
        __syncthreads();
        // load A and B tiles: 128 rows x 64 bf16 = 1024 x 16B chunks each
        #pragma unroll
        for (int i = 0; i < 4; i++) {
            int idx = tid + i * 256;       // 0..1023
            int r = idx >> 3;              // 0..127
            int c = idx & 7;               // 0..7 (16B chunks)
            *(float4*)&sA[r * SMEM_STRIDE + c * 8] =
                *(const float4*)&gA[(size_t)r * D_DIM + kc + c * 8];
            *(float4*)&sB[r * SMEM_STRIDE + c * 8] =
                *(const float4*)&gB[(size_t)r * D_DIM + kc + c * 8];
        }
        __syncthreads();

        #pragma unroll
        for (int ks = 0; ks < KC; ks += 16) {
            // A fragments: 2 m-tiles of 16x16
            uint32_t afr[2][4];
            #pragma unroll
            for (int mt = 0; mt < 2; mt++) {
                int row = wm * 32 + mt * 16 + (lane & 15);
                int col = ks + (lane >> 4) * 8;
                ldm_x4(afr[mt], smem_u32(&sA[row * SMEM_STRIDE + col]));
            }
            // B fragments: 4 ldmatrix, each covering two 16k x 8n tiles
            uint32_t bfr[4][4];
            #pragma unroll
            for (int nb = 0; nb < 4; nb++) {
                int row = wn * 64 + nb * 16 + (lane & 15);
                int col = ks + (lane >> 4) * 8;
                ldm_x4(bfr[nb], smem_u32(&sB[row * SMEM_STRIDE + col]));
            }
            #pragma unroll
            for (int mt = 0; mt < 2; mt++)
                #pragma unroll
                for (int nt = 0; nt < 8; nt++) {
                    uint32_t b0 = bfr[nt >> 1][(nt & 1)];
                    uint32_t b1 = bfr[nt >> 1][2 + (nt & 1)];
                    mma_bf16(acc[mt][nt], afr[mt], b0, b1);
                }
        }
    }

    // ---------------- epilogue: exp + mask + row sums ----------------
    const int g = lane >> 2;   // 0..7
    const int q = lane & 3;    // 0..3

    int labR[4];
    #pragma unroll
    for (int ri = 0; ri < 4; ri++) {
        int R = rowbase + wm * 32 + (ri >> 1) * 16 + g + (ri & 1) * 8;
        labR[ri] = labels[R & (B_ROWS - 1)];
    }

    float dsum[4] = {0, 0, 0, 0};
    float nsum[4] = {0, 0, 0, 0};

    #pragma unroll
    for (int nt = 0; nt < 8; nt++) {
        int cloc = wn * 64 + nt * 8 + q * 2;
        int lab0 = sLabN[cloc];
        int lab1 = sLabN[cloc + 1];
        int C0 = colbase + cloc;
        #pragma unroll
        for (int mt = 0; mt < 2; mt++) {
            #pragma unroll
            for (int half = 0; half < 2; half++) {
                int ri = mt * 2 + half;
                int R = rowbase + wm * 32 + mt * 16 + g + half * 8;
                float e0 = fast_exp2(acc[mt][nt][half * 2 + 0] * EXP_SCALE);
                float e1 = fast_exp2(acc[mt][nt][half * 2 + 1] * EXP_SCALE);
                if (R == C0)     e0 = 0.0f;
                if (R == C0 + 1) e1 = 0.0f;
                dsum[ri] += e0 + e1;
                nsum[ri] += (lab0 == labR[ri] ? e0 : 0.0f)
                          + (lab1 == labR[ri] ? e1 : 0.0f);
            }
        }
    }

    // reduce across the 4 lanes (q) that share each row
    #pragma unroll
    for (int s = 1; s <= 2; s <<= 1) {
        #pragma unroll
        for (int ri = 0; ri < 4; ri++) {
            dsum[ri] += __shfl_xor_sync(0xffffffffu, dsum[ri], s);
            nsum[ri] += __shfl_xor_sync(0xffffffffu, nsum[ri], s);
        }
    }
    if (q == 0) {
        #pragma unroll
        for (int ri = 0; ri < 4; ri++) {
            int R = rowbase + wm * 32 + (ri >> 1) * 16 + g + (ri & 1) * 8;
            atomicAdd(&g_den[R], dsum[ri]);
            atomicAdd(&g_nom[R], nsum[ri]);
        }
    }
}

// ---------------------------------------------------------------------------
// Kernel 3: loss = mean(log(den) - log(nom))
// ---------------------------------------------------------------------------
__global__ void loss_kernel(float* __restrict__ out) {
    __shared__ float red[32];
    int t = threadIdx.x;
    float s = 0.0f;
    for (int i = t; i < N2; i += blockDim.x)
        s += logf(g_den[i]) - logf(g_nom[i]);
    #pragma unroll
    for (int sh = 16; sh > 0; sh >>= 1)
        s += __shfl_xor_sync(0xffffffffu, s, sh);
    if ((t & 31) == 0) red[t >> 5] = s;
    __syncthreads();
    if (t < 32) {
        float v = (t < (int)(blockDim.x >> 5)) ? red[t] : 0.0f;
        #pragma unroll
        for (int sh = 16; sh > 0; sh >>= 1)
            v += __shfl_xor_sync(0xffffffffu, v, sh);
        if (t == 0) out[0] = v / (float)N2;
    }
}

// ---------------------------------------------------------------------------
extern "C" void kernel_launch(void* const* d_in, const int* in_sizes, int n_in,
                              void* d_out, int out_size) {
    const float* emb_i = (const float*)d_in[0];
    const float* emb_j = (const float*)d_in[1];
    const int* labels  = (const int*)d_in[2];
    float* out = (float*)d_out;

    zero_kernel<<<(N2 + 255) / 256, 256>>>();
    normalize_kernel<<<N2, 128>>>(emb_i, emb_j);
    dim3 grid(N2 / 128, N2 / 128);   // 64 x 64 CTAs
    sim_kernel<<<grid, 256>>>(labels);
    loss_kernel<<<1, 1024>>>(out);
}

// round 3
// speedup vs baseline: 2.4378x; 2.4378x over previous
#include <cuda_runtime.h>
#include <cuda_bf16.h>
#include <cstdint>

#define B_ROWS 4096
#define D_DIM 1024
#define N2 8192
#define NTILE 64                 // 8192 / 128 tiles per side
#define KC 64
#define SMEM_STRIDE 72           // bf16: 64 payload + 8 pad (conflict-free ldmatrix)
#define TILE_BYTES (128 * SMEM_STRIDE * 2)          // one operand tile: 18432 B
#define STAGE_BYTES (2 * TILE_BYTES)                // A + B per stage: 36864 B
#define SMEM_TOTAL (2 * STAGE_BYTES + 1024)

// exp(sim/T) with T=0.5: exp(2*sim) = exp2(sim * 2*log2(e))
#define EXP_SCALE 2.8853900817779268f

__device__ __nv_bfloat16 g_reps[(size_t)N2 * D_DIM];
__device__ float g_nom[N2];
__device__ float g_den[N2];

// ------------------------------ helpers -----------------------------------
__device__ __forceinline__ uint32_t smem_u32(const void* p) {
    return (uint32_t)__cvta_generic_to_shared(p);
}
__device__ __forceinline__ float fast_exp2(float x) {
    float y; asm("ex2.approx.f32 %0, %1;" : "=f"(y) : "f"(x)); return y;
}
__device__ __forceinline__ void ldm_x4(uint32_t r[4], uint32_t saddr) {
    asm volatile("ldmatrix.sync.aligned.m8n8.x4.shared.b16 {%0,%1,%2,%3}, [%4];\n"
                 : "=r"(r[0]), "=r"(r[1]), "=r"(r[2]), "=r"(r[3])
                 : "r"(saddr));
}
__device__ __forceinline__ void mma_bf16(float c[4], const uint32_t a[4],
                                         uint32_t b0, uint32_t b1) {
    asm volatile(
        "mma.sync.aligned.m16n8k16.row.col.f32.bf16.bf16.f32 "
        "{%0,%1,%2,%3}, {%4,%5,%6,%7}, {%8,%9}, {%0,%1,%2,%3};\n"
        : "+f"(c[0]), "+f"(c[1]), "+f"(c[2]), "+f"(c[3])
        : "r"(a[0]), "r"(a[1]), "r"(a[2]), "r"(a[3]), "r"(b0), "r"(b1));
}
__device__ __forceinline__ void cp16(uint32_t s, const void* g) {
    asm volatile("cp.async.cg.shared.global [%0], [%1], 16;" :: "r"(s), "l"(g));
}
__device__ __forceinline__ void cp_commit() {
    asm volatile("cp.async.commit_group;" ::: "memory");
}
template <int N> __device__ __forceinline__ void cp_wait() {
    asm volatile("cp.async.wait_group %0;" :: "n"(N) : "memory");
}

// ---------------------------------------------------------------------------
// Kernel 0: zero accumulators + output (graph replays re-zero every call)
// ---------------------------------------------------------------------------
__global__ void zero_kernel(float* out) {
    int i = blockIdx.x * blockDim.x + threadIdx.x;
    if (i < N2) { g_nom[i] = 0.0f; g_den[i] = 0.0f; }
    if (i == 0) out[0] = 0.0f;
}

// ---------------------------------------------------------------------------
// Kernel 1: L2-normalize rows of [emb_i; emb_j] -> bf16 reps
// ---------------------------------------------------------------------------
__global__ void normalize_kernel(const float* __restrict__ emb_i,
                                 const float* __restrict__ emb_j) {
    int row = blockIdx.x;
    const float* src = (row < B_ROWS)
        ? emb_i + (size_t)row * D_DIM
        : emb_j + (size_t)(row - B_ROWS) * D_DIM;
    int t = threadIdx.x;
    const float4* s4 = (const float4*)src;
    float4 v0 = s4[t];
    float4 v1 = s4[t + 128];
    float ss = v0.x*v0.x + v0.y*v0.y + v0.z*v0.z + v0.w*v0.w
             + v1.x*v1.x + v1.y*v1.y + v1.z*v1.z + v1.w*v1.w;
    #pragma unroll
    for (int s = 16; s > 0; s >>= 1)
        ss += __shfl_xor_sync(0xffffffffu, ss, s);
    __shared__ float wsum[4];
    if ((t & 31) == 0) wsum[t >> 5] = ss;
    __syncthreads();
    float total = wsum[0] + wsum[1] + wsum[2] + wsum[3];
    float scale = 1.0f / fmaxf(sqrtf(total), 1e-12f);

    __nv_bfloat162* d2 = (__nv_bfloat162*)(g_reps + (size_t)row * D_DIM);
    d2[2*t + 0]       = __floats2bfloat162_rn(v0.x*scale, v0.y*scale);
    d2[2*t + 1]       = __floats2bfloat162_rn(v0.z*scale, v0.w*scale);
    d2[2*(t+128) + 0] = __floats2bfloat162_rn(v1.x*scale, v1.y*scale);
    d2[2*(t+128) + 1] = __floats2bfloat162_rn(v1.z*scale, v1.w*scale);
}

// ---------------------------------------------------------------------------
// Kernel 2: fused sim-GEMM + exp + masked sums, UPPER-TRIANGLE tiles only.
// sim is symmetric, masks are symmetric -> off-diagonal tiles add row sums
// to den/nom[R] AND column sums to den/nom[C]. 2080 tiles instead of 4096.
// CTA tile 128x128, 2-stage cp.async pipeline, warp tile 32x64 (mma 16x8x16).
// ---------------------------------------------------------------------------
__device__ __forceinline__ void load_tiles(uint32_t sA, uint32_t sB,
                                           const __nv_bfloat16* gA,
                                           const __nv_bfloat16* gB,
                                           int kc, int tid) {
    #pragma unroll
    for (int i = 0; i < 4; i++) {
        int idx = tid + i * 256;           // 0..1023
        int r = idx >> 3, cb = idx & 7;    // 128 rows x 8 16B-chunks
        uint32_t off = r * (SMEM_STRIDE * 2) + cb * 16;
        cp16(sA + off, gA + (size_t)r * D_DIM + kc + cb * 8);
        cp16(sB + off, gB + (size_t)r * D_DIM + kc + cb * 8);
    }
}

__global__ void __launch_bounds__(256, 2)
sim_kernel(const int* __restrict__ labels) {
    extern __shared__ char dsm[];
    uint32_t base = smem_u32(dsm);
    int* sLab = (int*)dsm;                       // 128 col labels
    uint32_t abase = base + 1024;                // stages (16B aligned)

    // decode upper-triangle tile index
    int idx = blockIdx.x;
    int bm = 0;
    while (idx >= NTILE - bm) { idx -= NTILE - bm; bm++; }
    int bn = bm + idx;
    const bool diag = (bm == bn);

    const int rowbase = bm * 128, colbase = bn * 128;
    const int tid = threadIdx.x;
    const int warp = tid >> 5, lane = tid & 31;
    const int wm = warp >> 1;   // 0..3
    const int wn = warp & 1;    // 0..1

    if (tid < 128) sLab[tid] = labels[(colbase + tid) & (B_ROWS - 1)];

    float acc[2][8][4];
    #pragma unroll
    for (int mt = 0; mt < 2; mt++)
        #pragma unroll
        for (int nt = 0; nt < 8; nt++)
            #pragma unroll
            for (int i = 0; i < 4; i++) acc[mt][nt][i] = 0.0f;

    const __nv_bfloat16* gA = g_reps + (size_t)rowbase * D_DIM;
    const __nv_bfloat16* gB = g_reps + (size_t)colbase * D_DIM;

    // prologue: 2 stages
    load_tiles(abase, abase + TILE_BYTES, gA, gB, 0, tid);
    cp_commit();
    load_tiles(abase + STAGE_BYTES, abase + STAGE_BYTES + TILE_BYTES, gA, gB, KC, tid);
    cp_commit();
    __syncthreads();   // sLab visible

    #pragma unroll 1
    for (int c = 0; c < D_DIM / KC; c++) {
        int s = c & 1;
        uint32_t stA = abase + s * STAGE_BYTES;
        uint32_t stB = stA + TILE_BYTES;

        cp_wait<1>();
        __syncthreads();

        #pragma unroll
        for (int ks = 0; ks < KC; ks += 16) {
            uint32_t afr[2][4];
            #pragma unroll
            for (int mt = 0; mt < 2; mt++) {
                int row = wm * 32 + mt * 16 + (lane & 15);
                int col = ks + (lane >> 4) * 8;
                ldm_x4(afr[mt], stA + row * (SMEM_STRIDE * 2) + col * 2);
            }
            uint32_t bfr[4][4];
            #pragma unroll
            for (int nb = 0; nb < 4; nb++) {
                int row = wn * 64 + nb * 16 + (lane & 15);
                int col = ks + (lane >> 4) * 8;
                ldm_x4(bfr[nb], stB + row * (SMEM_STRIDE * 2) + col * 2);
            }
            #pragma unroll
            for (int mt = 0; mt < 2; mt++)
                #pragma unroll
                for (int nt = 0; nt < 8; nt++)
                    mma_bf16(acc[mt][nt], afr[mt],
                             bfr[nt >> 1][nt & 1], bfr[nt >> 1][2 + (nt & 1)]);
        }

        __syncthreads();           // all warps done reading stage s
        int nc = c + 2;
        if (nc < D_DIM / KC)
            load_tiles(stA, stB, gA, gB, nc * KC, tid);
        cp_commit();               // empty group in tail keeps counts uniform
    }

    // ---------------- epilogue ----------------
    const int g = lane >> 2;   // 0..7  (row within 8-row group)
    const int q = lane & 3;    // 0..3  (col pair)

    int labR[4];
    #pragma unroll
    for (int ri = 0; ri < 4; ri++) {
        int R = rowbase + wm * 32 + (ri >> 1) * 16 + g + (ri & 1) * 8;
        labR[ri] = labels[R & (B_ROWS - 1)];
    }

    float dsum[4] = {0, 0, 0, 0};
    float nsum[4] = {0, 0, 0, 0};

    #pragma unroll
    for (int nt = 0; nt < 8; nt++) {
        int cloc = wn * 64 + nt * 8 + q * 2;
        int lab0 = sLab[cloc];
        int lab1 = sLab[cloc + 1];
        int C0 = colbase + cloc;
        float cse0 = 0.0f, cse1 = 0.0f, csn0 = 0.0f, csn1 = 0.0f;

        #pragma unroll
        for (int mt = 0; mt < 2; mt++) {
            #pragma unroll
            for (int half = 0; half < 2; half++) {
                int ri = mt * 2 + half;
                float e0 = fast_exp2(acc[mt][nt][half * 2 + 0] * EXP_SCALE);
                float e1 = fast_exp2(acc[mt][nt][half * 2 + 1] * EXP_SCALE);
                if (diag) {
                    int R = rowbase + wm * 32 + mt * 16 + g + half * 8;
                    if (R == C0)     e0 = 0.0f;
                    if (R == C0 + 1) e1 = 0.0f;
                }
                bool p0 = (lab0 == labR[ri]);
                bool p1 = (lab1 == labR[ri]);
                dsum[ri] += e0 + e1;
                nsum[ri] += (p0 ? e0 : 0.0f) + (p1 ? e1 : 0.0f);
                if (!diag) {
                    cse0 += e0; cse1 += e1;
                    csn0 += p0 ? e0 : 0.0f;
                    csn1 += p1 ? e1 : 0.0f;
                }
            }
        }

        if (!diag) {
            // reduce column partials across g (lanes sharing q): masks 4,8,16
            #pragma unroll
            for (int sh = 4; sh <= 16; sh <<= 1) {
                cse0 += __shfl_xor_sync(0xffffffffu, cse0, sh);
                cse1 += __shfl_xor_sync(0xffffffffu, cse1, sh);
                csn0 += __shfl_xor_sync(0xffffffffu, csn0, sh);
                csn1 += __shfl_xor_sync(0xffffffffu, csn1, sh);
            }
            if (g == 0) {
                atomicAdd(&g_den[C0],     cse0);
                atomicAdd(&g_den[C0 + 1], cse1);
                atomicAdd(&g_nom[C0],     csn0);
                atomicAdd(&g_nom[C0 + 1], csn1);
            }
        }
    }

    // reduce row partials across the 4 q-lanes sharing each row
    #pragma unroll
    for (int sh = 1; sh <= 2; sh <<= 1) {
        #pragma unroll
        for (int ri = 0; ri < 4; ri++) {
            dsum[ri] += __shfl_xor_sync(0xffffffffu, dsum[ri], sh);
            nsum[ri] += __shfl_xor_sync(0xffffffffu, nsum[ri], sh);
        }
    }
    if (q == 0) {
        #pragma unroll
        for (int ri = 0; ri < 4; ri++) {
            int R = rowbase + wm * 32 + (ri >> 1) * 16 + g + (ri & 1) * 8;
            atomicAdd(&g_den[R], dsum[ri]);
            atomicAdd(&g_nom[R], nsum[ri]);
        }
    }
}

// ---------------------------------------------------------------------------
// Kernel 3: loss = mean(log(den) - log(nom))
// ---------------------------------------------------------------------------
__global__ void loss_kernel(float* __restrict__ out) {
    int i = blockIdx.x * blockDim.x + threadIdx.x;   // 8 x 1024 = 8192
    float s = logf(g_den[i]) - logf(g_nom[i]);
    #pragma unroll
    for (int sh = 16; sh > 0; sh >>= 1)
        s += __shfl_xor_sync(0xffffffffu, s, sh);
    __shared__ float red[32];
    int t = threadIdx.x;
    if ((t & 31) == 0) red[t >> 5] = s;
    __syncthreads();
    if (t < 32) {
        float v = red[t];
        #pragma unroll
        for (int sh = 16; sh > 0; sh >>= 1)
            v += __shfl_xor_sync(0xffffffffu, v, sh);
        if (t == 0) atomicAdd(out, v / (float)N2);
    }
}

// ---------------------------------------------------------------------------
extern "C" void kernel_launch(void* const* d_in, const int* in_sizes, int n_in,
                              void* d_out, int out_size) {
    const float* emb_i = (const float*)d_in[0];
    const float* emb_j = (const float*)d_in[1];
    const int* labels  = (const int*)d_in[2];
    float* out = (float*)d_out;

    cudaFuncSetAttribute(sim_kernel,
                         cudaFuncAttributeMaxDynamicSharedMemorySize, SMEM_TOTAL);

    zero_kernel<<<(N2 + 255) / 256, 256>>>(out);
    normalize_kernel<<<N2, 128>>>(emb_i, emb_j);
    int ntiles = NTILE * (NTILE + 1) / 2;     // 2080 upper-triangle tiles
    sim_kernel<<<ntiles, 256, SMEM_TOTAL>>>(labels);
    loss_kernel<<<8, 1024>>>(out);
}

// round 5
// speedup vs baseline: 2.6231x; 1.0760x over previous
#include <cuda_runtime.h>
#include <cuda_bf16.h>
#include <cstdint>

#define B_ROWS 4096
#define D_DIM 1024
#define N2 8192
#define NTILE 64                 // 8192 / 128 tiles per side
#define DP 512                   // row length in u16 (fp8 pairs)
#define KC16 64                  // u16 per K-chunk = 128 fp8 = 128 bytes/row
#define NCHUNK 8
#define SMEM_STRIDE 72           // u16: 64 payload + 8 pad (conflict-free ldmatrix)
#define TILE_BYTES (128 * SMEM_STRIDE * 2)          // 18432 B
#define STAGE_BYTES (2 * TILE_BYTES)                // A + B per stage
#define SMEM_TOTAL (2 * STAGE_BYTES + 1024)

// rows pre-scaled by 64 -> acc = 4096 * sim ; exp(sim/0.5) = exp2(acc * SC)
#define EXP_SCALE (2.8853900817779268f / 4096.0f)
#define FP8_SCALE 64.0f

__device__ uint16_t g_reps[(size_t)N2 * DP];   // e4m3 pairs
__device__ float g_nom[N2];
__device__ float g_den[N2];

// ------------------------------ helpers -----------------------------------
__device__ __forceinline__ uint32_t smem_u32(const void* p) {
    return (uint32_t)__cvta_generic_to_shared(p);
}
__device__ __forceinline__ float fast_exp2(float x) {
    float y; asm("ex2.approx.f32 %0, %1;" : "=f"(y) : "f"(x)); return y;
}
__device__ __forceinline__ void ldm_x4(uint32_t r[4], uint32_t saddr) {
    asm volatile("ldmatrix.sync.aligned.m8n8.x4.shared.b16 {%0,%1,%2,%3}, [%4];\n"
                 : "=r"(r[0]), "=r"(r[1]), "=r"(r[2]), "=r"(r[3])
                 : "r"(saddr));
}
__device__ __forceinline__ void mma_fp8(float c[4], const uint32_t a[4],
                                        uint32_t b0, uint32_t b1) {
    asm volatile(
        "mma.sync.aligned.m16n8k32.row.col.f32.e4m3.e4m3.f32 "
        "{%0,%1,%2,%3}, {%4,%5,%6,%7}, {%8,%9}, {%0,%1,%2,%3};\n"
        : "+f"(c[0]), "+f"(c[1]), "+f"(c[2]), "+f"(c[3])
        : "r"(a[0]), "r"(a[1]), "r"(a[2]), "r"(a[3]), "r"(b0), "r"(b1));
}
__device__ __forceinline__ uint16_t cvt_e4m3x2(float hi, float lo) {
    uint16_t r;
    asm("cvt.rn.satfinite.e4m3x2.f32 %0, %1, %2;" : "=h"(r) : "f"(hi), "f"(lo));
    return r;
}
__device__ __forceinline__ void cp16(uint32_t s, const void* g) {
    asm volatile("cp.async.cg.shared.global [%0], [%1], 16;" :: "r"(s), "l"(g));
}
__device__ __forceinline__ void cp_commit() {
    asm volatile("cp.async.commit_group;" ::: "memory");
}
template <int N> __device__ __forceinline__ void cp_wait() {
    asm volatile("cp.async.wait_group %0;" :: "n"(N) : "memory");
}

// ---------------------------------------------------------------------------
// Kernel 0: zero accumulators + output (graph replays re-zero every call)
// ---------------------------------------------------------------------------
__global__ void zero_kernel(float* out) {
    int i = blockIdx.x * blockDim.x + threadIdx.x;
    if (i < N2) { g_nom[i] = 0.0f; g_den[i] = 0.0f; }
    if (i == 0) out[0] = 0.0f;
}

// ---------------------------------------------------------------------------
// Kernel 1: L2-normalize rows of [emb_i; emb_j] -> fp8 e4m3 (x64) reps
// Each thread owns elems 4t..4t+3 (s4[t]) and 4(t+128).. (s4[t+128]):
// 4 floats -> 4 e4m3 -> one u32 at d32[t] and d32[t+128]. Row = 256 u32.
// ---------------------------------------------------------------------------
__global__ void normalize_kernel(const float* __restrict__ emb_i,
                                 const float* __restrict__ emb_j) {
    int row = blockIdx.x;
    const float* src = (row < B_ROWS)
        ? emb_i + (size_t)row * D_DIM
        : emb_j + (size_t)(row - B_ROWS) * D_DIM;
    int t = threadIdx.x;
    const float4* s4 = (const float4*)src;
    float4 v0 = s4[t];
    float4 v1 = s4[t + 128];
    float ss = v0.x*v0.x + v0.y*v0.y + v0.z*v0.z + v0.w*v0.w
             + v1.x*v1.x + v1.y*v1.y + v1.z*v1.z + v1.w*v1.w;
    #pragma unroll
    for (int s = 16; s > 0; s >>= 1)
        ss += __shfl_xor_sync(0xffffffffu, ss, s);
    __shared__ float wsum[4];
    if ((t & 31) == 0) wsum[t >> 5] = ss;
    __syncthreads();
    float total = wsum[0] + wsum[1] + wsum[2] + wsum[3];
    float scale = FP8_SCALE / fmaxf(sqrtf(total), 1e-12f);

    uint32_t* d32 = (uint32_t*)(g_reps + (size_t)row * DP);
    uint16_t p01 = cvt_e4m3x2(v0.y * scale, v0.x * scale);
    uint16_t p23 = cvt_e4m3x2(v0.w * scale, v0.z * scale);
    d32[t] = (uint32_t)p01 | ((uint32_t)p23 << 16);
    uint16_t q01 = cvt_e4m3x2(v1.y * scale, v1.x * scale);
    uint16_t q23 = cvt_e4m3x2(v1.w * scale, v1.z * scale);
    d32[t + 128] = (uint32_t)q01 | ((uint32_t)q23 << 16);
}

// ---------------------------------------------------------------------------
// Kernel 2: fused fp8 sim-GEMM + exp + masked sums, upper-triangle tiles.
// ---------------------------------------------------------------------------
__device__ __forceinline__ void load_tiles(uint32_t sA, uint32_t sB,
                                           const uint16_t* gA,
                                           const uint16_t* gB,
                                           int kc16, int tid) {
    #pragma unroll
    for (int i = 0; i < 4; i++) {
        int idx = tid + i * 256;           // 0..1023
        int r = idx >> 3, cb = idx & 7;    // 128 rows x 8 16B-chunks
        uint32_t off = r * (SMEM_STRIDE * 2) + cb * 16;
        cp16(sA + off, gA + (size_t)r * DP + kc16 + cb * 8);
        cp16(sB + off, gB + (size_t)r * DP + kc16 + cb * 8);
    }
}

__global__ void __launch_bounds__(256, 2)
sim_kernel(const int* __restrict__ labels) {
    extern __shared__ char dsm[];
    uint32_t base = smem_u32(dsm);
    int* sLab = (int*)dsm;                       // 128 col labels
    uint32_t abase = base + 1024;

    int idx = blockIdx.x;
    int bm = 0;
    while (idx >= NTILE - bm) { idx -= NTILE - bm; bm++; }
    int bn = bm + idx;
    const bool diag = (bm == bn);

    const int rowbase = bm * 128, colbase = bn * 128;
    const int tid = threadIdx.x;
    const int warp = tid >> 5, lane = tid & 31;
    const int wm = warp >> 1;
    const int wn = warp & 1;

    if (tid < 128) sLab[tid] = labels[(colbase + tid) & (B_ROWS - 1)];

    float acc[2][8][4];
    #pragma unroll
    for (int mt = 0; mt < 2; mt++)
        #pragma unroll
        for (int nt = 0; nt < 8; nt++)
            #pragma unroll
            for (int i = 0; i < 4; i++) acc[mt][nt][i] = 0.0f;

    const uint16_t* gA = g_reps + (size_t)rowbase * DP;
    const uint16_t* gB = g_reps + (size_t)colbase * DP;

    load_tiles(abase, abase + TILE_BYTES, gA, gB, 0, tid);
    cp_commit();
    load_tiles(abase + STAGE_BYTES, abase + STAGE_BYTES + TILE_BYTES, gA, gB, KC16, tid);
    cp_commit();
    __syncthreads();   // sLab visible

    #pragma unroll 1
    for (int c = 0; c < NCHUNK; c++) {
        int s = c & 1;
        uint32_t stA = abase + s * STAGE_BYTES;
        uint32_t stB = stA + TILE_BYTES;

        cp_wait<1>();
        __syncthreads();

        #pragma unroll
        for (int ks = 0; ks < KC16; ks += 16) {      // 16 u16 = 32 fp8 per mma
            uint32_t afr[2][4];
            #pragma unroll
            for (int mt = 0; mt < 2; mt++) {
                int row = wm * 32 + mt * 16 + (lane & 15);
                int col = ks + (lane >> 4) * 8;
                ldm_x4(afr[mt], stA + row * (SMEM_STRIDE * 2) + col * 2);
            }
            uint32_t bfr[4][4];
            #pragma unroll
            for (int nb = 0; nb < 4; nb++) {
                int row = wn * 64 + nb * 16 + (lane & 15);
                int col = ks + (lane >> 4) * 8;
                ldm_x4(bfr[nb], stB + row * (SMEM_STRIDE * 2) + col * 2);
            }
            #pragma unroll
            for (int mt = 0; mt < 2; mt++)
                #pragma unroll
                for (int nt = 0; nt < 8; nt++)
                    mma_fp8(acc[mt][nt], afr[mt],
                            bfr[nt >> 1][nt & 1], bfr[nt >> 1][2 + (nt & 1)]);
        }

        __syncthreads();
        int nc = c + 2;
        if (nc < NCHUNK)
            load_tiles(stA, stB, gA, gB, nc * KC16, tid);
        cp_commit();
    }

    // ---------------- epilogue ----------------
    const int g = lane >> 2;
    const int q = lane & 3;

    int labR[4];
    #pragma unroll
    for (int ri = 0; ri < 4; ri++) {
        int R = rowbase + wm * 32 + (ri >> 1) * 16 + g + (ri & 1) * 8;
        labR[ri] = labels[R & (B_ROWS - 1)];
    }

    float dsum[4] = {0, 0, 0, 0};
    float nsum[4] = {0, 0, 0, 0};

    #pragma unroll
    for (int nt = 0; nt < 8; nt++) {
        int cloc = wn * 64 + nt * 8 + q * 2;
        int lab0 = sLab[cloc];
        int lab1 = sLab[cloc + 1];
        int C0 = colbase + cloc;
        float cse0 = 0.0f, cse1 = 0.0f, csn0 = 0.0f, csn1 = 0.0f;

        #pragma unroll
        for (int mt = 0; mt < 2; mt++) {
            #pragma unroll
            for (int half = 0; half < 2; half++) {
                int ri = mt * 2 + half;
                float e0 = fast_exp2(acc[mt][nt][half * 2 + 0] * EXP_SCALE);
                float e1 = fast_exp2(acc[mt][nt][half * 2 + 1] * EXP_SCALE);
                if (diag) {
                    int R = rowbase + wm * 32 + mt * 16 + g + half * 8;
                    if (R == C0)     e0 = 0.0f;
                    if (R == C0 + 1) e1 = 0.0f;
                }
                bool p0 = (lab0 == labR[ri]);
                bool p1 = (lab1 == labR[ri]);
                dsum[ri] += e0 + e1;
                nsum[ri] += (p0 ? e0 : 0.0f) + (p1 ? e1 : 0.0f);
                if (!diag) {
                    cse0 += e0; cse1 += e1;
                    csn0 += p0 ? e0 : 0.0f;
                    csn1 += p1 ? e1 : 0.0f;
                }
            }
        }

        if (!diag) {
            #pragma unroll
            for (int sh = 4; sh <= 16; sh <<= 1) {
                cse0 += __shfl_xor_sync(0xffffffffu, cse0, sh);
                cse1 += __shfl_xor_sync(0xffffffffu, cse1, sh);
                csn0 += __shfl_xor_sync(0xffffffffu, csn0, sh);
                csn1 += __shfl_xor_sync(0xffffffffu, csn1, sh);
            }
            if (g == 0) {
                atomicAdd(&g_den[C0],     cse0);
                atomicAdd(&g_den[C0 + 1], cse1);
                atomicAdd(&g_nom[C0],     csn0);
                atomicAdd(&g_nom[C0 + 1], csn1);
            }
        }
    }

    #pragma unroll
    for (int sh = 1; sh <= 2; sh <<= 1) {
        #pragma unroll
        for (int ri = 0; ri < 4; ri++) {
            dsum[ri] += __shfl_xor_sync(0xffffffffu, dsum[ri], sh);
            nsum[ri] += __shfl_xor_sync(0xffffffffu, nsum[ri], sh);
        }
    }
    if (q == 0) {
        #pragma unroll
        for (int ri = 0; ri < 4; ri++) {
            int R = rowbase + wm * 32 + (ri >> 1) * 16 + g + (ri & 1) * 8;
            atomicAdd(&g_den[R], dsum[ri]);
            atomicAdd(&g_nom[R], nsum[ri]);
        }
    }
}

// ---------------------------------------------------------------------------
// Kernel 3: loss = mean(log(den) - log(nom))
// ---------------------------------------------------------------------------
__global__ void loss_kernel(float* __restrict__ out) {
    int i = blockIdx.x * blockDim.x + threadIdx.x;
    float s = logf(g_den[i]) - logf(g_nom[i]);
    #pragma unroll
    for (int sh = 16; sh > 0; sh >>= 1)
        s += __shfl_xor_sync(0xffffffffu, s, sh);
    __shared__ float red[32];
    int t = threadIdx.x;
    if ((t & 31) == 0) red[t >> 5] = s;
    __syncthreads();
    if (t < 32) {
        float v = red[t];
        #pragma unroll
        for (int sh = 16; sh > 0; sh >>= 1)
            v += __shfl_xor_sync(0xffffffffu, v, sh);
        if (t == 0) atomicAdd(out, v / (float)N2);
    }
}

// ---------------------------------------------------------------------------
extern "C" void kernel_launch(void* const* d_in, const int* in_sizes, int n_in,
                              void* d_out, int out_size) {
    const float* emb_i = (const float*)d_in[0];
    const float* emb_j = (const float*)d_in[1];
    const int* labels  = (const int*)d_in[2];
    float* out = (float*)d_out;

    cudaFuncSetAttribute(sim_kernel,
                         cudaFuncAttributeMaxDynamicSharedMemorySize, SMEM_TOTAL);

    zero_kernel<<<(N2 + 255) / 256, 256>>>(out);
    normalize_kernel<<<N2, 128>>>(emb_i, emb_j);
    int ntiles = NTILE * (NTILE + 1) / 2;
    sim_kernel<<<ntiles, 256, SMEM_TOTAL>>>(labels);
    loss_kernel<<<8, 1024>>>(out);
}